// round 16
// baseline (speedup 1.0000x reference)
#include <cuda_runtime.h>
#include <cstdint>

// D-FPS (B=8, N=32768, npoint=2048) + gather xyz -> out (B,3,2048) fp32.
//
// One 8-CTA cluster per batch (64 CTAs, 128 threads = 4 warps). Each thread
// owns 32 points, PACKED f32x2 in registers; running-min temp in registers.
// Per iteration (NO barrier.cluster in the loop -- one-way mbarrier
// rendezvous instead):
//   - packed add/mul.rn.f32x2 distance update (per-lane .rn => bit-exact)
//   - warp argmax via redux.sync (float bits of v>=0 are u32-monotone),
//     min-index tie-break == jnp.argmax first-occurrence
//   - CTA argmax in warp0 via redux; lanes 0..7 push {key,x,y,z} to cluster
//     CTA dst==lane IN PARALLEL (mapa + st.shared::cluster) and then
//     mbarrier.arrive.release.cluster on dst's LOCAL mbar (release orders
//     the same thread's prior data stores)
//   - ALL threads HW-sleep on their local mbar via mbarrier.try_wait.parity
//     (acquire.cluster) -- completion needs only the 8 one-way remote
//     arrives (~215cyc DSMEM hop) + wakeup, no cluster-wide round trip
//   - every thread picks the cluster winner from its own smem slots.
// Two mbars + slot buffers alternate by parity (p=j&1, parity of use n:
// ((j-1)>>1)&1). Early arrives for the next phase accumulate safely by
// mbarrier semantics. Slot reuse: reads(j) -> syncA(j+1) -> leader's
// release-arrive(j+1) -> writer's wait(j+1) -> writer's stores(j+2).

constexpr int BATCH   = 8;
constexpr int NPTS    = 32768;
constexpr int NPOINT  = 2048;
constexpr int CLUSTER = 8;
constexpr int T       = 128;
constexpr int PER_CTA = NPTS / CLUSTER;  // 4096
constexpr int P       = PER_CTA / T;     // 32 points / thread
constexpr int NPAIR   = P / 2;           // 16 packed pairs
constexpr int NW      = T / 32;          // 4 warps

__device__ __forceinline__ uint32_t smem_u32(const void* p) {
    uint32_t a;
    asm("{ .reg .u64 t; cvta.to.shared.u64 t, %1; cvt.u32.u64 %0, t; }"
        : "=r"(a) : "l"(p));
    return a;
}

extern __shared__ float s_dyn[];  // sx[4096] | sy[4096] | sz[4096] = 48KB

__global__ __launch_bounds__(T, 1) __cluster_dims__(CLUSTER, 1, 1)
void fps_cluster_kernel(const float* __restrict__ xyz_t, float* __restrict__ out)
{
    const int b = blockIdx.x >> 3;
    uint32_t rank;
    asm("mov.u32 %0, %%cluster_ctarank;" : "=r"(rank));

    const float* __restrict__ xs = xyz_t + (size_t)b * 3 * NPTS;
    const float* __restrict__ ys = xs + NPTS;
    const float* __restrict__ zs = xs + 2 * NPTS;
    float* __restrict__ ob = out + (size_t)b * 3 * NPOINT;

    const int tid = threadIdx.x;
    const int w = tid >> 5, l = tid & 31;
    const int pbase = (int)rank * PER_CTA;

    float* sx = s_dyn;
    float* sy = s_dyn + PER_CTA;
    float* sz = s_dyn + 2 * PER_CTA;

    __shared__ uint32_t s_wv[NW], s_wi[NW];
    __shared__ unsigned long long s_key[2][CLUSTER];
    __shared__ float4 s_co[2][CLUSTER];
    __shared__ unsigned long long s_mbar[2];

    // ---- load coords: smem table + packed registers ----
    unsigned long long xp[NPAIR], yp[NPAIR], zp[NPAIR];
    float tmp[P];
#pragma unroll
    for (int q = 0; q < NPAIR; ++q) {
        const int g0 = pbase + (2 * q)     * T + tid;
        const int g1 = pbase + (2 * q + 1) * T + tid;
        const float ax0 = xs[g0], ax1 = xs[g1];
        const float ay0 = ys[g0], ay1 = ys[g1];
        const float az0 = zs[g0], az1 = zs[g1];
        sx[(2*q)   * T + tid] = ax0;  sx[(2*q+1) * T + tid] = ax1;
        sy[(2*q)   * T + tid] = ay0;  sy[(2*q+1) * T + tid] = ay1;
        sz[(2*q)   * T + tid] = az0;  sz[(2*q+1) * T + tid] = az1;
        asm("mov.b64 %0, {%1, %2};" : "=l"(xp[q]) : "f"(ax0), "f"(ax1));
        asm("mov.b64 %0, {%1, %2};" : "=l"(yp[q]) : "f"(ay0), "f"(ay1));
        asm("mov.b64 %0, {%1, %2};" : "=l"(zp[q]) : "f"(az0), "f"(az1));
        tmp[2*q] = 1e10f; tmp[2*q+1] = 1e10f;
    }

    const uint32_t mb0 = smem_u32(&s_mbar[0]);
    const uint32_t mb1 = smem_u32(&s_mbar[1]);
    if (tid == 0) {
        asm volatile("mbarrier.init.shared::cta.b64 [%0], %1;"
                     :: "r"(mb0), "r"(CLUSTER) : "memory");
        asm volatile("mbarrier.init.shared::cta.b64 [%0], %1;"
                     :: "r"(mb1), "r"(CLUSTER) : "memory");
    }
    // mbarrier init + smem tables must be cluster-visible before any remote op
    asm volatile("barrier.cluster.arrive.aligned;" ::: "memory");
    asm volatile("barrier.cluster.wait.aligned;" ::: "memory");

    float lx = __ldg(xs), ly = __ldg(ys), lz = __ldg(zs);  // idx[0] = 0
    if (rank == 0 && tid == 0) {
        ob[0] = lx; ob[NPOINT] = ly; ob[2 * NPOINT] = lz;
    }

    for (int j = 1; j < NPOINT; ++j) {
        // packed negated center (per-lane duplicate)
        unsigned long long nlx2, nly2, nlz2;
        {
            const float nx = -lx, ny = -ly, nz = -lz;
            asm("mov.b64 %0, {%1, %1};" : "=l"(nlx2) : "f"(nx));
            asm("mov.b64 %0, {%1, %1};" : "=l"(nly2) : "f"(ny));
            asm("mov.b64 %0, {%1, %1};" : "=l"(nlz2) : "f"(nz));
        }

        float bv = -1.0f;
        int   bs = 0;
#pragma unroll
        for (int q = 0; q < NPAIR; ++q) {
            unsigned long long dx, dy, dz, qx, qy, qz, s01, acc;
            asm("add.rn.f32x2 %0, %1, %2;" : "=l"(dx) : "l"(xp[q]), "l"(nlx2));
            asm("add.rn.f32x2 %0, %1, %2;" : "=l"(dy) : "l"(yp[q]), "l"(nly2));
            asm("add.rn.f32x2 %0, %1, %2;" : "=l"(dz) : "l"(zp[q]), "l"(nlz2));
            asm("mul.rn.f32x2 %0, %1, %1;" : "=l"(qx) : "l"(dx));
            asm("mul.rn.f32x2 %0, %1, %1;" : "=l"(qy) : "l"(dy));
            asm("mul.rn.f32x2 %0, %1, %1;" : "=l"(qz) : "l"(dz));
            asm("add.rn.f32x2 %0, %1, %2;" : "=l"(s01) : "l"(qx), "l"(qy));
            asm("add.rn.f32x2 %0, %1, %2;" : "=l"(acc) : "l"(s01), "l"(qz));
            float d0, d1;
            asm("mov.b64 {%0, %1}, %2;" : "=f"(d0), "=f"(d1) : "l"(acc));
            float t0 = fminf(tmp[2*q], d0);     tmp[2*q] = t0;
            if (t0 > bv) { bv = t0; bs = 2*q; }
            float t1 = fminf(tmp[2*q+1], d1);   tmp[2*q+1] = t1;
            if (t1 > bv) { bv = t1; bs = 2*q+1; }
        }
        const uint32_t idx = (uint32_t)(pbase + bs * T + tid);

        // ---- warp argmax via redux (float bits of v>=0 are u32-monotone) ----
        const uint32_t vb   = __float_as_uint(bv);
        const uint32_t vmax = __reduce_max_sync(0xffffffffu, vb);
        const uint32_t imin = __reduce_min_sync(0xffffffffu,
                                   (vb == vmax) ? idx : 0xffffffffu);
        if (l == 0) { s_wv[w] = vmax; s_wi[w] = imin; }
        __syncthreads();   // sync A: warp candidates visible; anchors the
                           // happens-before chain for slot reuse

        const int p = j & 1;
        const uint32_t mbar_a = p ? mb1 : mb0;

        if (w == 0) {
            const uint32_t v  = (l < NW) ? s_wv[l] : 0u;
            const uint32_t ii = (l < NW) ? s_wi[l] : 0xffffffffu;
            const uint32_t vm = __reduce_max_sync(0xffffffffu, v);
            const uint32_t im = __reduce_min_sync(0xffffffffu,
                                    (v == vm) ? ii : 0xffffffffu);
            // lanes 0..7 push data + arrive to cluster CTA dst==lane in
            // parallel; arrive.release orders this thread's prior stores.
            if (l < CLUSTER) {
                const int li = (int)im - pbase;      // winner is in own range
                const float cx = sx[li], cy = sy[li], cz = sz[li];  // LDS bcast
                const unsigned long long key =
                    ((unsigned long long)vm << 32) | (uint32_t)(~im);
                unsigned long long xyp;
                asm("mov.b64 %0, {%1, %2};" : "=l"(xyp) : "f"(cx), "f"(cy));
                const uint32_t zb = __float_as_uint(cz);
                const uint32_t ka = smem_u32(&s_key[p][rank]);
                const uint32_t ca = smem_u32(&s_co[p][rank]);
                const int dco = (int)(ca - ka);
                const int dmb = (int)(mbar_a - ka);
                uint32_t rk;
                asm volatile("mapa.shared::cluster.u32 %0, %1, %2;"
                             : "=r"(rk) : "r"(ka), "r"(l));
                asm volatile("st.shared::cluster.b64 [%0], %1;"
                             :: "r"(rk), "l"(key) : "memory");
                asm volatile("st.shared::cluster.b64 [%0], %1;"
                             :: "r"(rk + dco), "l"(xyp) : "memory");
                asm volatile("st.shared::cluster.b32 [%0+8], %1;"
                             :: "r"(rk + dco), "r"(zb) : "memory");
                asm volatile(
                    "mbarrier.arrive.release.cluster.shared::cluster.b64 _, [%0];"
                    :: "r"(rk + dmb) : "memory");
            }
        }

        // ---- HW-sleep wait for the 8 one-way arrives (acquire.cluster) ----
        {
            const uint32_t par = (uint32_t)(((j - 1) >> 1) & 1);
            uint32_t done;
            asm volatile(
                "{\n\t.reg .pred pd;\n\t"
                "mbarrier.try_wait.parity.acquire.cluster.shared::cta.b64 pd, [%1], %2;\n\t"
                "selp.b32 %0, 1, 0, pd;\n\t}"
                : "=r"(done) : "r"(mbar_a), "r"(par) : "memory");
            if (!done) {
                asm volatile(
                    "{\n\t.reg .pred P1;\n\t"
                    "W_%=:\n\t"
                    "mbarrier.try_wait.parity.acquire.cluster.shared::cta.b64 P1, [%0], %1, 0x989680;\n\t"
                    "@P1 bra.uni D_%=;\n\t"
                    "bra.uni W_%=;\n\t"
                    "D_%=:\n\t}"
                    :: "r"(mbar_a), "r"(par) : "memory");
            }
        }

        // ---- every thread picks the cluster winner locally ----
        unsigned long long wk = s_key[p][0];
        int wc = 0;
#pragma unroll
        for (int c = 1; c < CLUSTER; ++c) {
            const unsigned long long kk = s_key[p][c];
            if (kk > wk) { wk = kk; wc = c; }
        }
        const float4 co = s_co[p][wc];
        lx = co.x; ly = co.y; lz = co.z;

        if (rank == 0 && tid == 0) {
            ob[j]              = lx;
            ob[NPOINT + j]     = ly;
            ob[2 * NPOINT + j] = lz;
        }
    }

    // no CTA may exit while peers may still target its smem/mbar
    asm volatile("barrier.cluster.arrive.aligned;" ::: "memory");
    asm volatile("barrier.cluster.wait.aligned;" ::: "memory");
}

extern "C" void kernel_launch(void* const* d_in, const int* in_sizes, int n_in,
                              void* d_out, int out_size)
{
    (void)in_sizes; (void)n_in; (void)out_size;
    const float* xyz_t = (const float*)d_in[1];   // points_xyz_t: (B, 3, N)
    float* out = (float*)d_out;                   // (B, 3, NPOINT)

    // Opt in to >48KB-total smem (48KB dynamic + ~0.4KB static). Host-side
    // attribute call: nothing enqueued on the stream, capture-safe,
    // deterministic and idempotent.
    const int dyn_bytes = 3 * PER_CTA * (int)sizeof(float);   // 49152
    cudaFuncSetAttribute(fps_cluster_kernel,
                         cudaFuncAttributeMaxDynamicSharedMemorySize, dyn_bytes);

    fps_cluster_kernel<<<BATCH * CLUSTER, T, dyn_bytes>>>(xyz_t, out);
}

// round 17
// speedup vs baseline: 1.2264x; 1.2264x over previous
#include <cuda_runtime.h>
#include <cstdint>

// D-FPS (B=8, N=32768, npoint=2048) + gather xyz -> out (B,3,2048) fp32.
//
// One 8-CTA cluster per batch (64 CTAs, 128 threads = 4 warps). Each thread
// owns 32 points, PACKED f32x2 in registers; running-min temp in registers.
// Per iteration:
//   - packed add/mul.rn.f32x2 distance update (per-lane .rn => bit-exact)
//   - warp argmax via redux.sync (float bits of v>=0 are u32-monotone),
//     min-index tie-break == jnp.argmax first-occurrence; warp leaders stage
//     ONE packed u64 key {val_bits, ~idx} (single STS.64)
//   - CTA argmax in warp0 (u64 keys, max == lexicographic (val, ~idx));
//     lanes 0..7 push {key, x,y,z} to cluster CTA dst==lane in parallel via
//     PRE-HOISTED mapa addresses (loop-invariant per parity); winner coords
//     from the CTA-local smem coord table (LDS, not L2)
//   - ONE barrier.cluster (arrive releases the remote stores, wait acquires)
//   - every thread picks the cluster winner: 4x LDS.128 (ulonglong2) +
//     balanced depth-3 compare tree.
// Slots double-buffered by parity: a same-parity overwrite for iter j+2 can
// only be issued after the cluster barrier of iter j+1, which post-dates all
// reads of the iter-j slots.

constexpr int BATCH   = 8;
constexpr int NPTS    = 32768;
constexpr int NPOINT  = 2048;
constexpr int CLUSTER = 8;
constexpr int T       = 128;
constexpr int PER_CTA = NPTS / CLUSTER;  // 4096
constexpr int P       = PER_CTA / T;     // 32 points / thread
constexpr int NPAIR   = P / 2;           // 16 packed pairs
constexpr int NW      = T / 32;          // 4 warps

__device__ __forceinline__ uint32_t smem_u32(const void* p) {
    uint32_t a;
    asm("{ .reg .u64 t; cvta.to.shared.u64 t, %1; cvt.u32.u64 %0, t; }"
        : "=r"(a) : "l"(p));
    return a;
}

extern __shared__ float s_dyn[];  // sx[4096] | sy[4096] | sz[4096] = 48KB

__global__ __launch_bounds__(T, 1) __cluster_dims__(CLUSTER, 1, 1)
void fps_cluster_kernel(const float* __restrict__ xyz_t, float* __restrict__ out)
{
    const int b = blockIdx.x >> 3;
    uint32_t rank;
    asm("mov.u32 %0, %%cluster_ctarank;" : "=r"(rank));

    const float* __restrict__ xs = xyz_t + (size_t)b * 3 * NPTS;
    const float* __restrict__ ys = xs + NPTS;
    const float* __restrict__ zs = xs + 2 * NPTS;
    float* __restrict__ ob = out + (size_t)b * 3 * NPOINT;

    const int tid = threadIdx.x;
    const int w = tid >> 5, l = tid & 31;
    const int pbase = (int)rank * PER_CTA;

    float* sx = s_dyn;
    float* sy = s_dyn + PER_CTA;
    float* sz = s_dyn + 2 * PER_CTA;

    __shared__ unsigned long long s_wkey[NW];
    __shared__ __align__(16) unsigned long long s_key[2][CLUSTER];
    __shared__ float4 s_co[2][CLUSTER];

    // ---- load coords: smem table + packed registers ----
    unsigned long long xp[NPAIR], yp[NPAIR], zp[NPAIR];
    float tmp[P];
#pragma unroll
    for (int q = 0; q < NPAIR; ++q) {
        const int g0 = pbase + (2 * q)     * T + tid;
        const int g1 = pbase + (2 * q + 1) * T + tid;
        const float ax0 = xs[g0], ax1 = xs[g1];
        const float ay0 = ys[g0], ay1 = ys[g1];
        const float az0 = zs[g0], az1 = zs[g1];
        sx[(2*q)   * T + tid] = ax0;  sx[(2*q+1) * T + tid] = ax1;
        sy[(2*q)   * T + tid] = ay0;  sy[(2*q+1) * T + tid] = ay1;
        sz[(2*q)   * T + tid] = az0;  sz[(2*q+1) * T + tid] = az1;
        asm("mov.b64 %0, {%1, %2};" : "=l"(xp[q]) : "f"(ax0), "f"(ax1));
        asm("mov.b64 %0, {%1, %2};" : "=l"(yp[q]) : "f"(ay0), "f"(ay1));
        asm("mov.b64 %0, {%1, %2};" : "=l"(zp[q]) : "f"(az0), "f"(az1));
        tmp[2*q] = 1e10f; tmp[2*q+1] = 1e10f;
    }

    // ---- hoist remote slot addresses (loop-invariant per parity) ----
    // rk_hoist[p] = address of s_key[p][rank] inside CTA (dst == l), l < 8.
    uint32_t rk_hoist[2];
    int dco_hoist;   // byte offset s_co[p][rank] - s_key[p][rank] (parity-inv)
    {
        const uint32_t ka0 = smem_u32(&s_key[0][rank]);
        const uint32_t ka1 = smem_u32(&s_key[1][rank]);
        const uint32_t ca0 = smem_u32(&s_co[0][rank]);
        dco_hoist = (int)(ca0 - ka0);
        const uint32_t dst = (l < CLUSTER) ? (uint32_t)l : 0u;
        asm("mapa.shared::cluster.u32 %0, %1, %2;"
            : "=r"(rk_hoist[0]) : "r"(ka0), "r"(dst));
        asm("mapa.shared::cluster.u32 %0, %1, %2;"
            : "=r"(rk_hoist[1]) : "r"(ka1), "r"(dst));
        // note: s_co[1] - s_key[1] == s_co[0] - s_key[0] by layout symmetry?
        // Not guaranteed by the compiler; compute per-parity co offset:
        const uint32_t ca1 = smem_u32(&s_co[1][rank]);
        (void)ca1;
    }
    const int dco0 = (int)(smem_u32(&s_co[0][rank]) - smem_u32(&s_key[0][rank]));
    const int dco1 = (int)(smem_u32(&s_co[1][rank]) - smem_u32(&s_key[1][rank]));
    (void)dco_hoist;

    float lx = __ldg(xs), ly = __ldg(ys), lz = __ldg(zs);  // idx[0] = 0
    if (rank == 0 && tid == 0) {
        ob[0] = lx; ob[NPOINT] = ly; ob[2 * NPOINT] = lz;
    }

    // DSMEM safety: peers fully launched before any remote store.
    asm volatile("barrier.cluster.arrive.aligned;" ::: "memory");
    asm volatile("barrier.cluster.wait.aligned;" ::: "memory");

    for (int j = 1; j < NPOINT; ++j) {
        // packed negated center (per-lane duplicate)
        unsigned long long nlx2, nly2, nlz2;
        {
            const float nx = -lx, ny = -ly, nz = -lz;
            asm("mov.b64 %0, {%1, %1};" : "=l"(nlx2) : "f"(nx));
            asm("mov.b64 %0, {%1, %1};" : "=l"(nly2) : "f"(ny));
            asm("mov.b64 %0, {%1, %1};" : "=l"(nlz2) : "f"(nz));
        }

        float bv = -1.0f;
        int   bs = 0;
#pragma unroll
        for (int q = 0; q < NPAIR; ++q) {
            unsigned long long dx, dy, dz, qx, qy, qz, s01, acc;
            asm("add.rn.f32x2 %0, %1, %2;" : "=l"(dx) : "l"(xp[q]), "l"(nlx2));
            asm("add.rn.f32x2 %0, %1, %2;" : "=l"(dy) : "l"(yp[q]), "l"(nly2));
            asm("add.rn.f32x2 %0, %1, %2;" : "=l"(dz) : "l"(zp[q]), "l"(nlz2));
            asm("mul.rn.f32x2 %0, %1, %1;" : "=l"(qx) : "l"(dx));
            asm("mul.rn.f32x2 %0, %1, %1;" : "=l"(qy) : "l"(dy));
            asm("mul.rn.f32x2 %0, %1, %1;" : "=l"(qz) : "l"(dz));
            asm("add.rn.f32x2 %0, %1, %2;" : "=l"(s01) : "l"(qx), "l"(qy));
            asm("add.rn.f32x2 %0, %1, %2;" : "=l"(acc) : "l"(s01), "l"(qz));
            float d0, d1;
            asm("mov.b64 {%0, %1}, %2;" : "=f"(d0), "=f"(d1) : "l"(acc));
            float t0 = fminf(tmp[2*q], d0);     tmp[2*q] = t0;
            if (t0 > bv) { bv = t0; bs = 2*q; }
            float t1 = fminf(tmp[2*q+1], d1);   tmp[2*q+1] = t1;
            if (t1 > bv) { bv = t1; bs = 2*q+1; }
        }
        const uint32_t idx = (uint32_t)(pbase + bs * T + tid);

        // ---- warp argmax via redux (float bits of v>=0 are u32-monotone) ----
        const uint32_t vb   = __float_as_uint(bv);
        const uint32_t vmax = __reduce_max_sync(0xffffffffu, vb);
        const uint32_t imin = __reduce_min_sync(0xffffffffu,
                                   (vb == vmax) ? idx : 0xffffffffu);
        if (l == 0) {
            // single STS.64 of the packed key (monotone u64)
            s_wkey[w] = ((unsigned long long)vmax << 32) | (uint32_t)(~imin);
        }
        __syncthreads();

        const int p = j & 1;

        if (w == 0) {
            // stage 2 over 4 u64 candidates; max == lexicographic winner
            const unsigned long long kk = (l < NW) ? s_wkey[l] : 0ull;
            uint32_t klo, khi;
            asm("mov.b64 {%0, %1}, %2;" : "=r"(klo), "=r"(khi) : "l"(kk));
            const uint32_t vm = __reduce_max_sync(0xffffffffu, khi);
            const uint32_t nim = __reduce_max_sync(0xffffffffu,
                                    (khi == vm) ? klo : 0u);  // max ~idx = min idx
            if (l < CLUSTER) {
                const uint32_t im = ~nim;
                const int li = (int)im - pbase;      // winner is in own range
                const float cx = sx[li], cy = sy[li], cz = sz[li];  // LDS bcast
                unsigned long long key;
                asm("mov.b64 %0, {%1, %2};" : "=l"(key) : "r"(nim), "r"(vm));
                unsigned long long xyp;
                asm("mov.b64 %0, {%1, %2};" : "=l"(xyp) : "f"(cx), "f"(cy));
                const uint32_t zb = __float_as_uint(cz);
                const uint32_t rk = rk_hoist[p];
                const int dco = p ? dco1 : dco0;
                asm volatile("st.shared::cluster.b64 [%0], %1;"
                             :: "r"(rk), "l"(key) : "memory");
                asm volatile("st.shared::cluster.b64 [%0], %1;"
                             :: "r"(rk + dco), "l"(xyp) : "memory");
                asm volatile("st.shared::cluster.b32 [%0+8], %1;"
                             :: "r"(rk + dco), "r"(zb) : "memory");
            }
        }

        // arrive = release (orders the shared::cluster stores), wait = acquire
        asm volatile("barrier.cluster.arrive.aligned;" ::: "memory");
        asm volatile("barrier.cluster.wait.aligned;" ::: "memory");

        // ---- pick cluster winner: 4x LDS.128 + depth-3 tree ----
        {
            const ulonglong2* kp =
                reinterpret_cast<const ulonglong2*>(&s_key[p][0]);
            const ulonglong2 p0 = kp[0], p1 = kp[1], p2 = kp[2], p3 = kp[3];
            unsigned long long k0 = p0.x, k1 = p0.y, k2 = p1.x, k3 = p1.y;
            unsigned long long k4 = p2.x, k5 = p2.y, k6 = p3.x, k7 = p3.y;
            int c0 = 0, c2 = 2, c4 = 4, c6 = 6;
            if (k1 > k0) { k0 = k1; c0 = 1; }
            if (k3 > k2) { k2 = k3; c2 = 3; }
            if (k5 > k4) { k4 = k5; c4 = 5; }
            if (k7 > k6) { k6 = k7; c6 = 7; }
            if (k2 > k0) { k0 = k2; c0 = c2; }
            if (k6 > k4) { k4 = k6; c4 = c6; }
            if (k4 > k0) { k0 = k4; c0 = c4; }
            const float4 co = s_co[p][c0];
            lx = co.x; ly = co.y; lz = co.z;
        }

        if (rank == 0 && tid == 0) {
            ob[j]              = lx;
            ob[NPOINT + j]     = ly;
            ob[2 * NPOINT + j] = lz;
        }
    }
}

extern "C" void kernel_launch(void* const* d_in, const int* in_sizes, int n_in,
                              void* d_out, int out_size)
{
    (void)in_sizes; (void)n_in; (void)out_size;
    const float* xyz_t = (const float*)d_in[1];   // points_xyz_t: (B, 3, N)
    float* out = (float*)d_out;                   // (B, 3, NPOINT)

    // Opt in to >48KB-total smem (48KB dynamic + ~0.4KB static). Host-side
    // attribute call: nothing enqueued on the stream, capture-safe,
    // deterministic and idempotent.
    const int dyn_bytes = 3 * PER_CTA * (int)sizeof(float);   // 49152
    cudaFuncSetAttribute(fps_cluster_kernel,
                         cudaFuncAttributeMaxDynamicSharedMemorySize, dyn_bytes);

    fps_cluster_kernel<<<BATCH * CLUSTER, T, dyn_bytes>>>(xyz_t, out);
}